// round 6
// baseline (speedup 1.0000x reference)
#include <cuda_runtime.h>
#include <math.h>

#define Bn 512   // batch
#define Nn 512   // nodes / input dim / hidden state size
#define Hn 256   // hidden_dim (message)

__device__ float g_m[Bn * Hn];          // relu message   [512,256]
__device__ float g_gh[Bn * 3 * Nn];     // x@W_hh^T + b   [512,1536]

// ---------------------------------------------------------------------------
// Kernel 1 (heterogeneous):
//   blocks [0, 512):   per-batch agg (adj streaming) + fused message MLP
//   blocks [512, 704): gh GEMM  gh[b,j] = dot(x[b,:], W_hh[j,:]) + b_hh[j]
// Agg blocks first so the HBM stream starts immediately; GEMM fills compute.
// ---------------------------------------------------------------------------
#define AGG_BLOCKS Bn
#define GH_BLOCKS 192   // (512/64) * (1536/64)

__global__ __launch_bounds__(256, 2)
void k1_agg_m_gh(const float* __restrict__ x,
                 const float* __restrict__ adj,
                 const float* __restrict__ W_msg,
                 const float* __restrict__ b_msg,
                 const float* __restrict__ W_hh,
                 const float* __restrict__ b_hh)
{
    const int t = threadIdx.x;

    if (blockIdx.x < AGG_BLOCKS) {
        // ---------------- agg + message for one batch row
        __shared__ float4 xs4[Nn / 4];   // x[b,:] as float4
        __shared__ float  aggs[Nn];

        const int b = blockIdx.x;
        if (t < Nn / 4) xs4[t] = ((const float4*)(x + b * Nn))[t];
        __syncthreads();

        const int warp = t >> 5;
        const int lane = t & 31;
        const int sub  = lane >> 3;   // 0..3 : row within group of 4
        const int sl   = lane & 7;    // 0..7 : 8 lanes per row
        const float4* adjb = (const float4*)(adj + (size_t)b * Nn * Nn);

        // each warp owns 64 rows; processes 4 rows at a time, 8 lanes/row
        const int rbeg = warp * 64;
        for (int r0 = rbeg; r0 < rbeg + 64; r0 += 4) {
            const int row = r0 + sub;
            const float4* rp = adjb + row * (Nn / 4);
            float acc = 0.f;
#pragma unroll
            for (int j = 0; j < 16; j++) {
                float4 a  = __ldcs(&rp[sl + 8 * j]);   // streaming: 16 indep LDG.128
                float4 xv = xs4[sl + 8 * j];
                acc += a.x * xv.x + a.y * xv.y + a.z * xv.z + a.w * xv.w;
            }
            // reduce across the 8 lanes of this row
            acc += __shfl_down_sync(0xFFFFFFFFu, acc, 4);
            acc += __shfl_down_sync(0xFFFFFFFFu, acc, 2);
            acc += __shfl_down_sync(0xFFFFFFFFu, acc, 1);
            if (sl == 0) aggs[row] = acc;
        }
        __syncthreads();

        // m[b][t] = relu(dot(aggs, W_msg[t,:]) + b_msg[t]),  t in [0,256)
        float acc = b_msg[t];
        const float4* wr = (const float4*)(W_msg + t * Nn);
#pragma unroll 8
        for (int k4 = 0; k4 < Nn / 4; k4++) {
            float4 w = wr[k4];
            const float* ap = &aggs[k4 * 4];
            acc += w.x * ap[0] + w.y * ap[1] + w.z * ap[2] + w.w * ap[3];
        }
        g_m[b * Hn + t] = fmaxf(acc, 0.f);
    } else {
        // ---------------- gh GEMM: [512,1536] = x[512,512] @ W_hh[1536,512]^T + b_hh
        __shared__ float As[16][68];
        __shared__ float Bs[16][68];

        const int gid = blockIdx.x - AGG_BLOCKS;
        const int bn = gid % 24;
        const int bm = gid / 24;
        const int m0 = bm * 64;
        const int n0 = bn * 64;

        const int ldr = t >> 2;
        const int kg  = (t & 3) * 4;
        const int ty = t >> 4;
        const int tx = t & 15;

        float acc[4][4];
#pragma unroll
        for (int i = 0; i < 4; i++)
#pragma unroll
            for (int j = 0; j < 4; j++) acc[i][j] = 0.f;

        for (int k0 = 0; k0 < Nn; k0 += 16) {
            float4 a = *(const float4*)&x[(m0 + ldr) * Nn + k0 + kg];
            float4 b = *(const float4*)&W_hh[(n0 + ldr) * Nn + k0 + kg];
            __syncthreads();
            As[kg + 0][ldr] = a.x; As[kg + 1][ldr] = a.y;
            As[kg + 2][ldr] = a.z; As[kg + 3][ldr] = a.w;
            Bs[kg + 0][ldr] = b.x; Bs[kg + 1][ldr] = b.y;
            Bs[kg + 2][ldr] = b.z; Bs[kg + 3][ldr] = b.w;
            __syncthreads();
#pragma unroll
            for (int kk = 0; kk < 16; kk++) {
                float ra[4], rb[4];
                *(float4*)ra = *(const float4*)&As[kk][ty * 4];
                *(float4*)rb = *(const float4*)&Bs[kk][tx * 4];
#pragma unroll
                for (int i = 0; i < 4; i++)
#pragma unroll
                    for (int j = 0; j < 4; j++)
                        acc[i][j] += ra[i] * rb[j];
            }
        }
#pragma unroll
        for (int i = 0; i < 4; i++) {
            const int row = m0 + ty * 4 + i;
#pragma unroll
            for (int j = 0; j < 4; j++) {
                const int col = n0 + tx * 4 + j;
                g_gh[row * (3 * Nn) + col] = acc[i][j] + b_hh[col];
            }
        }
    }
}

// ---------------------------------------------------------------------------
// Kernel 2: gi GEMM (K=256) three gate sections + gate math + output
//   tiles 32x32, BK=32, 256 threads, 2x2 microtile x 3 gates, grid=256
// ---------------------------------------------------------------------------
__device__ __forceinline__ float fast_sigmoid(float v) {
    return 1.f / (1.f + __expf(-v));
}
__device__ __forceinline__ float fast_tanh(float v) {
    // 1 - 2/(e^{2v}+1): correct limits at +/- inf, ~1e-7 rel err
    return 1.f - 2.f / (__expf(2.f * v) + 1.f);
}

__global__ __launch_bounds__(256)
void k2_gates(const float* __restrict__ x,
              const float* __restrict__ W_ih,
              const float* __restrict__ b_ih,
              float* __restrict__ out)
{
    __shared__ float As[32][34];
    __shared__ float Br[32][34];
    __shared__ float Bz[32][34];
    __shared__ float Bq[32][34];

    const int t  = threadIdx.x;
    const int bm = blockIdx.x >> 4;     // 0..15
    const int bn = blockIdx.x & 15;     // 0..15
    const int m0 = bm * 32;
    const int n0 = bn * 32;

    const int row = t >> 3;             // 0..31 (tile row for loads)
    const int kq  = (t & 7) * 4;        // 0,4,...,28

    const int ty = t >> 4;              // 0..15 -> out rows ty*2..
    const int tx = t & 15;              // 0..15 -> out cols tx*2..

    float aR[2][2] = {}, aZ[2][2] = {}, aQ[2][2] = {};

    for (int k0 = 0; k0 < Hn; k0 += 32) {
        float4 a = *(const float4*)&g_m[(m0 + row) * Hn + k0 + kq];
        float4 r = *(const float4*)&W_ih[(n0 + row) * Hn + k0 + kq];
        float4 z = *(const float4*)&W_ih[(Nn + n0 + row) * Hn + k0 + kq];
        float4 q = *(const float4*)&W_ih[(2 * Nn + n0 + row) * Hn + k0 + kq];
        __syncthreads();
        As[kq + 0][row] = a.x; As[kq + 1][row] = a.y; As[kq + 2][row] = a.z; As[kq + 3][row] = a.w;
        Br[kq + 0][row] = r.x; Br[kq + 1][row] = r.y; Br[kq + 2][row] = r.z; Br[kq + 3][row] = r.w;
        Bz[kq + 0][row] = z.x; Bz[kq + 1][row] = z.y; Bz[kq + 2][row] = z.z; Bz[kq + 3][row] = z.w;
        Bq[kq + 0][row] = q.x; Bq[kq + 1][row] = q.y; Bq[kq + 2][row] = q.z; Bq[kq + 3][row] = q.w;
        __syncthreads();
#pragma unroll
        for (int kk = 0; kk < 32; kk++) {
            float2 ra = *(const float2*)&As[kk][ty * 2];
            float2 rr = *(const float2*)&Br[kk][tx * 2];
            float2 rz = *(const float2*)&Bz[kk][tx * 2];
            float2 rq = *(const float2*)&Bq[kk][tx * 2];
            aR[0][0] += ra.x * rr.x; aR[0][1] += ra.x * rr.y;
            aR[1][0] += ra.y * rr.x; aR[1][1] += ra.y * rr.y;
            aZ[0][0] += ra.x * rz.x; aZ[0][1] += ra.x * rz.y;
            aZ[1][0] += ra.y * rz.x; aZ[1][1] += ra.y * rz.y;
            aQ[0][0] += ra.x * rq.x; aQ[0][1] += ra.x * rq.y;
            aQ[1][0] += ra.y * rq.x; aQ[1][1] += ra.y * rq.y;
        }
    }

#pragma unroll
    for (int i = 0; i < 2; i++) {
        const int orow = m0 + ty * 2 + i;
#pragma unroll
        for (int j = 0; j < 2; j++) {
            const int col = n0 + tx * 2 + j;
            const float i_r = aR[i][j] + __ldg(&b_ih[col]);
            const float i_z = aZ[i][j] + __ldg(&b_ih[Nn + col]);
            const float i_n = aQ[i][j] + __ldg(&b_ih[2 * Nn + col]);
            const float h_r = g_gh[orow * (3 * Nn) + col];
            const float h_z = g_gh[orow * (3 * Nn) + Nn + col];
            const float h_n = g_gh[orow * (3 * Nn) + 2 * Nn + col];
            const float rg = fast_sigmoid(i_r + h_r);
            const float zg = fast_sigmoid(i_z + h_z);
            const float ng = fast_tanh(i_n + rg * h_n);
            const float xv = x[orow * Nn + col];
            out[orow * Nn + col] = (1.f - zg) * ng + zg * xv;
        }
    }
}

extern "C" void kernel_launch(void* const* d_in, const int* in_sizes, int n_in,
                              void* d_out, int out_size)
{
    (void)in_sizes; (void)n_in; (void)out_size;
    const float* x     = (const float*)d_in[0];
    const float* adj   = (const float*)d_in[1];
    const float* W_msg = (const float*)d_in[2];
    const float* b_msg = (const float*)d_in[3];
    const float* W_ih  = (const float*)d_in[4];
    const float* b_ih  = (const float*)d_in[5];
    const float* W_hh  = (const float*)d_in[6];
    const float* b_hh  = (const float*)d_in[7];
    float* out = (float*)d_out;

    k1_agg_m_gh<<<AGG_BLOCKS + GH_BLOCKS, 256>>>(x, adj, W_msg, b_msg, W_hh, b_hh);
    k2_gates<<<256, 256>>>(x, W_ih, b_ih, out);
}